// round 14
// baseline (speedup 1.0000x reference)
#include <cuda_runtime.h>
#include <cuda_fp16.h>
#include <cstdint>

#define NB 16384
#define NKEY 64
#define ND 128
#define NU 128
#define NM 32
#define TB 128
#define NCH 35            // 2 main(f16) + 32 modes(fp8) + 1 bias(f16)
#define STGB 32768        // stage stride (f16 chunks 32KB, fp8 chunks use 16KB)
#define NSTAGE 4
#define NCONS 16
#define NTHR (NCONS * 32 + 32)
#define SK 16.0f          // fp8 K scaling

__device__ __align__(16) unsigned char g_Bf[NCH * STGB];

// ---------------------------------------------------------------------------
// pack helpers
// ---------------------------------------------------------------------------
__device__ __forceinline__ uint32_t h2pk(float a, float b) {   // low half = a
    __half2 h = __halves2half2(__float2half_rn(a), __float2half_rn(b));
    return *(uint32_t*)&h;
}
// 4 floats -> 4 e4m3 bytes, byte0 (LSB) = a
__device__ __forceinline__ uint32_t pk8(float a, float b, float c, float d) {
    uint16_t lo, hi;
    asm("cvt.rn.satfinite.e4m3x2.f32 %0, %1, %2;" : "=h"(lo) : "f"(b), "f"(a));
    asm("cvt.rn.satfinite.e4m3x2.f32 %0, %1, %2;" : "=h"(hi) : "f"(d), "f"(c));
    return (uint32_t)lo | ((uint32_t)hi << 16);
}

// ---------------------------------------------------------------------------
// prep_b (49 blocks x 256):
//  blocks 0..15 : K_sum/1024 hi+lo f16 chunks (chunks 0,1)  [outer 1/32 FIXED]
//  blocks 16..47: mode m -> fp8 chunk 2+m (K*SK, m16n8k32 frag order)
//  block  48    : bias chunk 34 (f16 frag order, K=32 zero-padded, /32 folded)
// ---------------------------------------------------------------------------
__global__ __launch_bounds__(256) void prep_b(const float* __restrict__ kernels,
                                              const float* __restrict__ biases)
{
    __shared__ float sbuf[32 * 132];
    const int bid = blockIdx.x, tid = threadIdx.x;

    if (bid < 16) {
        // ---- K_sum hi/lo; main term = x @ K_sum_raw / (32*32) ----
        const int ksn = bid >> 1, nh = bid & 1;
        float* S = sbuf;                 // [16][68]
        for (int i = tid; i < 16 * 64; i += 256) {
            const int kl = i >> 6, nl = i & 63, n = nh * 64 + nl;
            float s = 0.f;
            #pragma unroll 8
            for (int m = 0; m < NM; m++)
                s += kernels[(size_t)m * 16384 + (size_t)(ksn * 16 + kl) * 128 + n];
            S[kl * 68 + nl] = s * (1.0f / 1024.0f);      // <-- THE FIX (was 1/32)
        }
        __syncthreads();
        if (tid < 128) {
            const int jp = nh * 4 + (tid >> 5), l = tid & 31;
            const int g = l >> 2, t = l & 3;
            const int nel = (jp * 16 + g) - nh * 64, nol = nel + 8;
            const int k0 = 2 * t;
            float v[8] = { S[k0*68+nel], S[(k0+1)*68+nel], S[(k0+8)*68+nel], S[(k0+9)*68+nel],
                           S[k0*68+nol], S[(k0+1)*68+nol], S[(k0+8)*68+nol], S[(k0+9)*68+nol] };
            float hi[8], lo[8];
            #pragma unroll
            for (int i = 0; i < 8; i++) {
                __half h = __float2half_rn(v[i]);
                hi[i] = __half2float(h);
                lo[i] = v[i] - hi[i];
            }
            const size_t off = (size_t)((ksn * 8 + jp) * 32 + l) * 16;
            uint4 wh, wl;
            wh.x = h2pk(hi[0], hi[1]); wh.y = h2pk(hi[2], hi[3]);
            wh.z = h2pk(hi[4], hi[5]); wh.w = h2pk(hi[6], hi[7]);
            wl.x = h2pk(lo[0], lo[1]); wl.y = h2pk(lo[2], lo[3]);
            wl.z = h2pk(lo[4], lo[5]); wl.w = h2pk(lo[6], lo[7]);
            *(uint4*)(g_Bf + off) = wh;
            *(uint4*)(g_Bf + STGB + off) = wl;
        }
    } else if (bid < 48) {
        // ---- fp8 mode chunk ----
        const int m = bid - 16;
        const float* base = kernels + (size_t)m * 16384;
        unsigned char* dst = g_Bf + (size_t)(2 + m) * STGB;
        #pragma unroll 1
        for (int p = 0; p < 4; p++) {
            for (int i = tid; i < 32 * 128; i += 256) {
                const int kl = i >> 7, n = i & 127;
                sbuf[kl * 132 + n] = base[(size_t)(32 * p + kl) * 128 + n] * SK;
            }
            __syncthreads();
            {
                const int jp = tid >> 5, l = tid & 31;
                const int g = l >> 2, t = l & 3;
                const int ne = jp * 16 + g, no = ne + 8;
                const int kl = 4 * t;
                uint4 wv;
                wv.x = pk8(sbuf[kl*132+ne], sbuf[(kl+1)*132+ne],
                           sbuf[(kl+2)*132+ne], sbuf[(kl+3)*132+ne]);
                wv.y = pk8(sbuf[(kl+16)*132+ne], sbuf[(kl+17)*132+ne],
                           sbuf[(kl+18)*132+ne], sbuf[(kl+19)*132+ne]);
                wv.z = pk8(sbuf[kl*132+no], sbuf[(kl+1)*132+no],
                           sbuf[(kl+2)*132+no], sbuf[(kl+3)*132+no]);
                wv.w = pk8(sbuf[(kl+16)*132+no], sbuf[(kl+17)*132+no],
                           sbuf[(kl+18)*132+no], sbuf[(kl+19)*132+no]);
                *(uint4*)(dst + (size_t)((p * 8 + jp) * 32 + l) * 16) = wv;
            }
            __syncthreads();
        }
    } else {
        // ---- bias chunk (f16 layout, ksn<2 real, rest zero) ----
        unsigned char* dst = g_Bf + (size_t)34 * STGB;
        for (int i = tid; i < 2048; i += 256) {
            const int ksn = i >> 8, r = i & 255, jp = r >> 5, l = r & 31;
            const int g = l >> 2, t = l & 3;
            uint4 wv = {0u, 0u, 0u, 0u};
            if (ksn < 2) {
                const int ne = jp * 16 + g, no = ne + 8;
                const int k0 = ksn * 16 + 2 * t;
                const float sc = 1.0f / 32.0f;
                wv.x = h2pk(biases[k0*128+ne]*sc,     biases[(k0+1)*128+ne]*sc);
                wv.y = h2pk(biases[(k0+8)*128+ne]*sc, biases[(k0+9)*128+ne]*sc);
                wv.z = h2pk(biases[k0*128+no]*sc,     biases[(k0+1)*128+no]*sc);
                wv.w = h2pk(biases[(k0+8)*128+no]*sc, biases[(k0+9)*128+no]*sc);
            }
            *(uint4*)(dst + (size_t)i * 16) = wv;
        }
    }
}

// ---------------------------------------------------------------------------
// mbarrier helpers
// ---------------------------------------------------------------------------
__device__ __forceinline__ void mbar_init(uint32_t mbar, uint32_t cnt) {
    asm volatile("mbarrier.init.shared.b64 [%0], %1;" :: "r"(mbar), "r"(cnt) : "memory");
}
__device__ __forceinline__ void mbar_arrive(uint32_t mbar) {
    asm volatile("mbarrier.arrive.shared.b64 _, [%0];" :: "r"(mbar) : "memory");
}
__device__ __forceinline__ void mbar_expect_tx(uint32_t mbar, uint32_t bytes) {
    asm volatile("mbarrier.arrive.expect_tx.shared.b64 _, [%0], %1;"
                 :: "r"(mbar), "r"(bytes) : "memory");
}
__device__ __forceinline__ void mbar_wait(uint32_t mbar, uint32_t parity) {
    asm volatile(
        "{\n\t.reg .pred P;\n\t"
        "W%=:\n\t"
        "mbarrier.try_wait.parity.acquire.cta.shared::cta.b64 P, [%0], %1, 0x989680;\n\t"
        "@!P bra W%=;\n\t}"
        :: "r"(mbar), "r"(parity) : "memory");
}
__device__ __forceinline__ void bulk_copy(uint32_t dst, uint64_t src, uint32_t bytes,
                                          uint32_t mbar) {
    asm volatile(
        "cp.async.bulk.shared::cluster.global.mbarrier::complete_tx::bytes "
        "[%0], [%1], %2, [%3];"
        :: "r"(dst), "l"(src), "r"(bytes), "r"(mbar) : "memory");
}

// ---------------------------------------------------------------------------
// MMA wrappers
// ---------------------------------------------------------------------------
__device__ __forceinline__ void mma16816(float* c, const uint32_t* a,
                                         uint32_t b0, uint32_t b1) {
    asm volatile(
        "mma.sync.aligned.m16n8k16.row.col.f32.f16.f16.f32 "
        "{%0,%1,%2,%3}, {%4,%5,%6,%7}, {%8,%9}, {%0,%1,%2,%3};"
        : "+f"(c[0]), "+f"(c[1]), "+f"(c[2]), "+f"(c[3])
        : "r"(a[0]), "r"(a[1]), "r"(a[2]), "r"(a[3]), "r"(b0), "r"(b1));
}
__device__ __forceinline__ void mmafp8(float* c, const uint32_t* a,
                                       uint32_t b0, uint32_t b1) {
    asm volatile(
        "mma.sync.aligned.m16n8k32.row.col.f32.e4m3.e4m3.f32 "
        "{%0,%1,%2,%3}, {%4,%5,%6,%7}, {%8,%9}, {%0,%1,%2,%3};"
        : "+f"(c[0]), "+f"(c[1]), "+f"(c[2]), "+f"(c[3])
        : "r"(a[0]), "r"(a[1]), "r"(a[2]), "r"(a[3]), "r"(b0), "r"(b1));
}

// ---------------------------------------------------------------------------
// mma_kernel: 128 CTAs x 544 threads (R10/R11 structure).
// ---------------------------------------------------------------------------
#define SIM_OFF 0
#define MB_OFF  16896
#define KM_OFF  17024
#define KS_OFF  25472
#define B_OFF   58368
#define SMEM_BYTES 189440

__global__ __launch_bounds__(NTHR, 1) void mma_kernel(const float* __restrict__ x,
                                                      const float* __restrict__ key,
                                                      const float* __restrict__ sens,
                                                      const float* __restrict__ keys_map,
                                                      float* __restrict__ out)
{
    extern __shared__ __align__(16) unsigned char sm[];
    float* simS = (float*)(sm + SIM_OFF);

    uint32_t smb;
    asm("{ .reg .u64 t; cvta.to.shared.u64 t, %1; cvt.u32.u64 %0, t; }"
        : "=r"(smb) : "l"(sm));
    uint64_t gb;
    {
        const unsigned char* p = g_Bf;
        asm("cvta.to.global.u64 %0, %1;" : "=l"(gb) : "l"(p));
    }

    const int tid = threadIdx.x;
    const int l = tid & 31, w = tid >> 5;
    const int g = l >> 2, t = l & 3;
    const int row0 = blockIdx.x * TB;

    const uint32_t mb_full  = smb + MB_OFF;
    const uint32_t mb_empty = smb + MB_OFF + 32;

    if (tid == 0) {
        #pragma unroll
        for (int s = 0; s < NSTAGE; s++) {
            mbar_init(mb_full + 8 * s, 1);
            mbar_init(mb_empty + 8 * s, NCONS);
        }
    }
    {
        float* kmS = (float*)(sm + KM_OFF);
        float* ssS = kmS + 32 * 65;
        float* ksS = (float*)(sm + KS_OFF);
        for (int i = tid; i < NM * NKEY; i += NTHR)
            kmS[(i >> 6) * 65 + (i & 63)] = keys_map[i];
        for (int i = tid; i < TB * NKEY; i += NTHR)
            ksS[i] = key[(size_t)row0 * NKEY + i];
        if (tid < NM) ssS[tid] = sens[tid];
    }
    __syncthreads();

    if (w == NCONS) {
        // ------------------------------ producer ------------------------------
        if (l == 0) {
            #pragma unroll 1
            for (int c = 0; c < NCH; c++) {
                const int s = c & 3;
                const uint32_t u = (uint32_t)(c >> 2);
                const uint32_t bytes = (c < 2 || c == 34) ? 32768u : 16384u;
                mbar_wait(mb_empty + 8 * s, (u & 1u) ^ 1u);
                mbar_expect_tx(mb_full + 8 * s, bytes);
                bulk_copy(smb + B_OFF + s * STGB, gb + (uint64_t)c * STGB,
                          bytes, mb_full + 8 * s);
            }
        }
        return;
    }

    // ------------------------------ consumers ------------------------------
    const int rg = w >> 1, cg = w & 1;
    const int r0 = rg * 16 + g;
    const int r1 = r0 + 8;
    const float* x0 = x + (size_t)(row0 + r0) * ND;
    const float* x1 = x + (size_t)(row0 + r1) * ND;

    // ---- sim for this CTA's 128 rows ----
    {
        const float* kmS = (const float*)(sm + KM_OFF);
        const float* ssS = kmS + 32 * 65;
        const float* ksS = (const float*)(sm + KS_OFF);
        const int m = l;
        #pragma unroll 1
        for (int i = 0; i < 8; i++) {
            const int r = w * 8 + i;
            float d2 = 0.f;
            #pragma unroll
            for (int k = 0; k < NKEY; k++) {
                const float df = ksS[r * 64 + k] - kmS[m * 65 + k];
                d2 = fmaf(df, df, d2);
            }
            const float lg = ssS[m] / (sqrtf(d2) + 1.0f);
            float mx = lg;
            #pragma unroll
            for (int o = 16; o > 0; o >>= 1)
                mx = fmaxf(mx, __shfl_xor_sync(0xFFFFFFFFu, mx, o));
            const float e = __expf(lg - mx);
            float s = e;
            #pragma unroll
            for (int o = 16; o > 0; o >>= 1)
                s += __shfl_xor_sync(0xFFFFFFFFu, s, o);
            simS[r * 33 + m] = e / s;
        }
    }
    asm volatile("bar.sync 1, %0;" :: "n"(NCONS * 32) : "memory");

    float acc[8][4];
    #pragma unroll
    for (int nf = 0; nf < 8; nf++)
        #pragma unroll
        for (int i = 0; i < 4; i++) acc[nf][i] = 0.f;

    // ---- main term: chunks 0 (K_sum hi) and 1 (K_sum lo), f16 ----
    {
        uint32_t axm[8][4];
        #pragma unroll
        for (int j = 0; j < 8; j++) {
            const int k0 = j * 16 + 2 * t;
            float2 v0 = __ldg((const float2*)(x0 + k0));
            float2 v1 = __ldg((const float2*)(x0 + k0 + 8));
            float2 v2 = __ldg((const float2*)(x1 + k0));
            float2 v3 = __ldg((const float2*)(x1 + k0 + 8));
            axm[j][0] = h2pk(v0.x, v0.y);
            axm[j][1] = h2pk(v2.x, v2.y);
            axm[j][2] = h2pk(v1.x, v1.y);
            axm[j][3] = h2pk(v3.x, v3.y);
        }
        #pragma unroll 1
        for (int c = 0; c < 2; c++) {
            mbar_wait(mb_full + 8 * c, 0u);
            const uint4* bbb = (const uint4*)(sm + B_OFF + c * STGB);
            #pragma unroll
            for (int ksn = 0; ksn < 8; ksn++) {
                #pragma unroll
                for (int nfp = 0; nfp < 4; nfp++) {
                    uint4 Bp = bbb[(ksn * 8 + cg * 4 + nfp) * 32 + l];
                    mma16816(acc[2*nfp+0], axm[ksn], Bp.x, Bp.y);
                    mma16816(acc[2*nfp+1], axm[ksn], Bp.z, Bp.w);
                }
            }
            __syncwarp();
            if (l == 0) mbar_arrive(mb_empty + 8 * c);
        }
    }

    // ---- x -> loop-invariant e4m3 A fragments (m16n8k32 order) ----
    uint32_t ax8[4][4];
    #pragma unroll
    for (int j = 0; j < 4; j++) {
        const int kb = 32 * j + 4 * t;
        float4 v0 = __ldg((const float4*)(x0 + kb));
        float4 v1 = __ldg((const float4*)(x1 + kb));
        float4 v2 = __ldg((const float4*)(x0 + kb + 16));
        float4 v3 = __ldg((const float4*)(x1 + kb + 16));
        ax8[j][0] = pk8(v0.x, v0.y, v0.z, v0.w);
        ax8[j][1] = pk8(v1.x, v1.y, v1.z, v1.w);
        ax8[j][2] = pk8(v2.x, v2.y, v2.z, v2.w);
        ax8[j][3] = pk8(v3.x, v3.y, v3.z, v3.w);
    }

    // ---- correction: chunks 2..33, fp8 QMMA, fold (sim-1/32)/(SK*32) ----
    const float cf = 1.0f / (SK * 32.0f);
    #pragma unroll 1
    for (int c = 2; c < 34; c++) {
        const int s = c & 3;
        const uint32_t u = (uint32_t)(c >> 2);
        mbar_wait(mb_full + 8 * s, u & 1u);

        const int m = c - 2;
        const float coef0 = (simS[r0 * 33 + m] - 0.03125f) * cf;
        const float coef1 = (simS[r1 * 33 + m] - 0.03125f) * cf;

        const uint4* bbb = (const uint4*)(sm + B_OFF + s * STGB);
        #pragma unroll
        for (int nfp = 0; nfp < 4; nfp++) {
            float d[8];
            #pragma unroll
            for (int i = 0; i < 8; i++) d[i] = 0.f;
            #pragma unroll
            for (int j = 0; j < 4; j++) {
                uint4 Bp = bbb[(j * 8 + cg * 4 + nfp) * 32 + l];
                mmafp8(d,     ax8[j], Bp.x, Bp.y);
                mmafp8(d + 4, ax8[j], Bp.z, Bp.w);
            }
            acc[2*nfp+0][0] = fmaf(coef0, d[0], acc[2*nfp+0][0]);
            acc[2*nfp+0][1] = fmaf(coef0, d[1], acc[2*nfp+0][1]);
            acc[2*nfp+0][2] = fmaf(coef1, d[2], acc[2*nfp+0][2]);
            acc[2*nfp+0][3] = fmaf(coef1, d[3], acc[2*nfp+0][3]);
            acc[2*nfp+1][0] = fmaf(coef0, d[4], acc[2*nfp+1][0]);
            acc[2*nfp+1][1] = fmaf(coef0, d[5], acc[2*nfp+1][1]);
            acc[2*nfp+1][2] = fmaf(coef1, d[6], acc[2*nfp+1][2]);
            acc[2*nfp+1][3] = fmaf(coef1, d[7], acc[2*nfp+1][3]);
        }

        __syncwarp();
        if (l == 0) mbar_arrive(mb_empty + 8 * s);
    }

    // ---- bias chunk c=34 (stage 2, parity 0): A = full sim, k<32 ----
    {
        mbar_wait(mb_full + 8 * 2, 0u);
        const uint4* bbb = (const uint4*)(sm + B_OFF + 2 * STGB);
        #pragma unroll
        for (int ksn = 0; ksn < 2; ksn++) {
            const int k0 = ksn * 16 + 2 * t;
            uint32_t a0[4];
            a0[0] = h2pk(simS[r0*33 + k0],   simS[r0*33 + k0+1]);
            a0[1] = h2pk(simS[r1*33 + k0],   simS[r1*33 + k0+1]);
            a0[2] = h2pk(simS[r0*33 + k0+8], simS[r0*33 + k0+9]);
            a0[3] = h2pk(simS[r1*33 + k0+8], simS[r1*33 + k0+9]);
            #pragma unroll
            for (int nf2 = 0; nf2 < 4; nf2++) {
                uint4 Bp = bbb[(ksn * 8 + cg * 4 + nf2) * 32 + l];
                mma16816(acc[2*nf2+0], a0, Bp.x, Bp.y);
                mma16816(acc[2*nf2+1], a0, Bp.z, Bp.w);
            }
        }
    }

    // ---- epilogue ----
    {
        const int ra = row0 + r0, rb2 = row0 + r1;
        #pragma unroll
        for (int nf = 0; nf < 8; nf++) {
            const int col = cg * 64 + nf * 8 + 2 * t;
            float2 v0, v1;
            v0.x = acc[nf][0]; v0.y = acc[nf][1];
            v1.x = acc[nf][2]; v1.y = acc[nf][3];
            *(float2*)&out[(size_t)ra * NU + col] = v0;
            *(float2*)&out[(size_t)rb2 * NU + col] = v1;
        }
    }
}

// ---------------------------------------------------------------------------
extern "C" void kernel_launch(void* const* d_in, const int* in_sizes, int n_in,
                              void* d_out, int out_size)
{
    const float *key = 0, *x = 0, *sens = 0, *keys_map = 0, *kernels = 0, *biases = 0;
    for (int i = 0; i < n_in; i++) {
        switch (in_sizes[i]) {
            case NB * NKEY:    key      = (const float*)d_in[i]; break;
            case NB * ND:      x        = (const float*)d_in[i]; break;
            case NM:           sens     = (const float*)d_in[i]; break;
            case NM * NKEY:    keys_map = (const float*)d_in[i]; break;
            case NM * ND * NU: kernels  = (const float*)d_in[i]; break;
            case NM * NU:      biases   = (const float*)d_in[i]; break;
            default: break;
        }
    }
    float* out = (float*)d_out;

    cudaFuncSetAttribute(mma_kernel, cudaFuncAttributeMaxDynamicSharedMemorySize,
                         SMEM_BYTES);

    prep_b<<<49, 256>>>(kernels, biases);
    mma_kernel<<<NB / TB, NTHR, SMEM_BYTES>>>(x, key, sens, keys_map, out);
}